// round 1
// baseline (speedup 1.0000x reference)
#include <cuda_runtime.h>
#include <cstdint>

// Problem constants (FractalMoE: E=32, H=512, TOPK=4, B=2, S=1024)
#define NTOK   2048
#define HDIM   512
#define H2DIM  1024
#define NEXP   32
#define TOPK   4
#define NSLOT  (NTOK*TOPK)   // 8192

// ---------------- scratch (device globals; no allocation allowed) ----------
__device__ int   g_sel[NSLOT];
__device__ float g_wn[NSLOT];
__device__ int   g_off[NEXP+1];
__device__ int   g_tileoff[NEXP+1];
__device__ int   g_tok[NSLOT];
__device__ float g_tw[NSLOT];
__device__ int   g_pos[NSLOT];
__device__ float g_hidden[(size_t)NSLOT*H2DIM];   // 32 MiB
__device__ float g_partial[(size_t)NSLOT*HDIM];   // 16 MiB

// ---------------- packed f32x2 FMA helpers (FFMA2, 2x fp32 rate) -----------
__device__ __forceinline__ unsigned long long pk2(float lo, float hi) {
    unsigned long long r;
    asm("mov.b64 %0, {%1, %2};" : "=l"(r) : "f"(lo), "f"(hi));
    return r;
}
__device__ __forceinline__ void fma2(unsigned long long& d,
                                     unsigned long long a,
                                     unsigned long long b) {
    asm("fma.rn.f32x2 %0, %1, %2, %0;" : "+l"(d) : "l"(a), "l"(b));
}
__device__ __forceinline__ float2 upk2(unsigned long long v) {
    float lo, hi;
    asm("mov.b64 {%0, %1}, %2;" : "=f"(lo), "=f"(hi) : "l"(v));
    return make_float2(lo, hi);
}

// ---------------- 1) gating: softmax + top-4 + renormalize -----------------
// one warp per token, one lane per expert (E=32)
__global__ void gate_kernel(const float* __restrict__ x,
                            const float* __restrict__ gw) {
    int t    = blockIdx.x * (blockDim.x >> 5) + (threadIdx.x >> 5);
    int lane = threadIdx.x & 31;
    if (t >= NTOK) return;

    const float4* xv = (const float4*)(x + (size_t)t * HDIM);
    const float4* gv = (const float4*)(gw + (size_t)lane * HDIM);
    float acc = 0.f;
#pragma unroll 4
    for (int k = 0; k < HDIM/4; k++) {
        float4 a = xv[k], b = gv[k];
        acc += a.x*b.x + a.y*b.y + a.z*b.z + a.w*b.w;
    }
    // softmax over 32 lanes
    float m = acc;
    for (int o = 16; o; o >>= 1) m = fmaxf(m, __shfl_xor_sync(0xffffffffu, m, o));
    float p = __expf(acc - m);
    float s = p;
    for (int o = 16; o; o >>= 1) s += __shfl_xor_sync(0xffffffffu, s, o);
    float prob = p / s;

    // top-4 (tie-break: lower index wins, matching lax.top_k)
    float cur = prob, wsum = 0.f;
    float wv[TOPK]; int iv[TOPK];
#pragma unroll
    for (int it = 0; it < TOPK; it++) {
        float v = cur; int idx = lane;
        for (int o = 16; o; o >>= 1) {
            float v2 = __shfl_xor_sync(0xffffffffu, v, o);
            int   i2 = __shfl_xor_sync(0xffffffffu, idx, o);
            if (v2 > v || (v2 == v && i2 < idx)) { v = v2; idx = i2; }
        }
        wv[it] = v; iv[it] = idx; wsum += v;
        if (lane == idx) cur = -1.0f;
    }
    if (lane == 0) {
#pragma unroll
        for (int it = 0; it < TOPK; it++) {
            g_sel[t*TOPK + it] = iv[it];
            g_wn [t*TOPK + it] = wv[it] / wsum;
        }
    }
}

// ---------------- 2) routing: counts, offsets, scatter ---------------------
__global__ void route_kernel() {
    __shared__ int cnt[NEXP], run[NEXP], off_s[NEXP+1];
    int tid = threadIdx.x;
    if (tid < NEXP) { cnt[tid] = 0; run[tid] = 0; }
    __syncthreads();
    for (int i = tid; i < NSLOT; i += blockDim.x)
        atomicAdd(&cnt[g_sel[i]], 1);
    __syncthreads();
    if (tid == 0) {
        int o = 0, to = 0;
        for (int e = 0; e < NEXP; e++) {
            off_s[e] = o; g_off[e] = o; g_tileoff[e] = to;
            o  += cnt[e];
            to += (cnt[e] + 63) >> 6;
        }
        off_s[NEXP] = o; g_off[NEXP] = o; g_tileoff[NEXP] = to;
    }
    __syncthreads();
    for (int i = tid; i < NSLOT; i += blockDim.x) {
        int e = g_sel[i];
        int p = atomicAdd(&run[e], 1) + off_s[e];
        g_tok[p] = i >> 2;          // token id
        g_tw [p] = g_wn[i];         // combine weight
        g_pos[i] = p;               // token-slot -> sorted position
    }
}

// ---------------- 3) FFN1: hidden = silu(x Wg^T) * (x Wu^T) ----------------
// tile: 64 tokens x 128 hidden, K=512; 256 threads, microtile 4x8 (f32x2)
__global__ __launch_bounds__(256)
void ffn1_kernel(const float* __restrict__ x,
                 const float* __restrict__ wg,
                 const float* __restrict__ wu) {
    __shared__ float Xs[16][64];
    __shared__ float Gs[16][128];
    __shared__ float Us[16][128];
    __shared__ int rtok[64];
    __shared__ int toff[NEXP+1], ooff[NEXP+1];

    int tid = threadIdx.x;
    if (tid <= NEXP) { toff[tid] = g_tileoff[tid]; ooff[tid] = g_off[tid]; }
    __syncthreads();
    int nitems = toff[NEXP] * (H2DIM/128);   // tiles * 8
    int tx = tid & 15, ty = tid >> 4;
    int lr = tid >> 2, lkq = tid & 3;

    for (int item = blockIdx.x; item < nitems; item += gridDim.x) {
        int tIdx = item >> 3;
        int ht   = item & 7;
        int e = 0;
        while (toff[e+1] <= tIdx) e++;
        int tt    = tIdx - toff[e];
        int base  = ooff[e] + tt*64;
        int nrows = min(64, ooff[e+1] - base);

        __syncthreads();
        if (tid < 64) rtok[tid] = g_tok[base + min(tid, nrows-1)];
        __syncthreads();

        const float* xrow = x + (size_t)rtok[lr]*HDIM + lkq*4;
        const float* wgB  = wg + ((size_t)e*H2DIM + (size_t)ht*128)*HDIM;
        const float* wuB  = wu + ((size_t)e*H2DIM + (size_t)ht*128)*HDIM;

        unsigned long long accg[4][4] = {}, accu[4][4] = {};

        for (int k0 = 0; k0 < HDIM; k0 += 16) {
            float4 xa  = *(const float4*)(xrow + k0);
            float4 ga0 = *(const float4*)(wgB + (size_t)lr     *HDIM + k0 + lkq*4);
            float4 ga1 = *(const float4*)(wgB + (size_t)(64+lr)*HDIM + k0 + lkq*4);
            float4 ua0 = *(const float4*)(wuB + (size_t)lr     *HDIM + k0 + lkq*4);
            float4 ua1 = *(const float4*)(wuB + (size_t)(64+lr)*HDIM + k0 + lkq*4);
            __syncthreads();
            Xs[lkq*4+0][lr]=xa.x;  Xs[lkq*4+1][lr]=xa.y;  Xs[lkq*4+2][lr]=xa.z;  Xs[lkq*4+3][lr]=xa.w;
            Gs[lkq*4+0][lr]=ga0.x; Gs[lkq*4+1][lr]=ga0.y; Gs[lkq*4+2][lr]=ga0.z; Gs[lkq*4+3][lr]=ga0.w;
            Gs[lkq*4+0][64+lr]=ga1.x; Gs[lkq*4+1][64+lr]=ga1.y; Gs[lkq*4+2][64+lr]=ga1.z; Gs[lkq*4+3][64+lr]=ga1.w;
            Us[lkq*4+0][lr]=ua0.x; Us[lkq*4+1][lr]=ua0.y; Us[lkq*4+2][lr]=ua0.z; Us[lkq*4+3][lr]=ua0.w;
            Us[lkq*4+0][64+lr]=ua1.x; Us[lkq*4+1][64+lr]=ua1.y; Us[lkq*4+2][64+lr]=ua1.z; Us[lkq*4+3][64+lr]=ua1.w;
            __syncthreads();
#pragma unroll
            for (int kk = 0; kk < 16; kk++) {
                float4 bg0 = *(const float4*)&Gs[kk][tx*8];
                float4 bg1 = *(const float4*)&Gs[kk][tx*8+4];
                float4 bu0 = *(const float4*)&Us[kk][tx*8];
                float4 bu1 = *(const float4*)&Us[kk][tx*8+4];
                unsigned long long pg0 = pk2(bg0.x,bg0.y), pg1 = pk2(bg0.z,bg0.w);
                unsigned long long pg2 = pk2(bg1.x,bg1.y), pg3 = pk2(bg1.z,bg1.w);
                unsigned long long pu0 = pk2(bu0.x,bu0.y), pu1 = pk2(bu0.z,bu0.w);
                unsigned long long pu2 = pk2(bu1.x,bu1.y), pu3 = pk2(bu1.z,bu1.w);
#pragma unroll
                for (int i = 0; i < 4; i++) {
                    float a = Xs[kk][ty*4+i];
                    unsigned long long aa = pk2(a, a);
                    fma2(accg[i][0], aa, pg0); fma2(accg[i][1], aa, pg1);
                    fma2(accg[i][2], aa, pg2); fma2(accg[i][3], aa, pg3);
                    fma2(accu[i][0], aa, pu0); fma2(accu[i][1], aa, pu1);
                    fma2(accu[i][2], aa, pu2); fma2(accu[i][3], aa, pu3);
                }
            }
        }
        // epilogue: silu(g)*u, write hidden
#pragma unroll
        for (int i = 0; i < 4; i++) {
            int row = ty*4 + i;
            if (row < nrows) {
                float h[8];
#pragma unroll
                for (int jp = 0; jp < 4; jp++) {
                    float2 g = upk2(accg[i][jp]);
                    float2 u = upk2(accu[i][jp]);
                    h[2*jp  ] = u.x * g.x / (1.f + __expf(-g.x));
                    h[2*jp+1] = u.y * g.y / (1.f + __expf(-g.y));
                }
                float* dst = g_hidden + (size_t)(base+row)*H2DIM + ht*128 + tx*8;
                *(float4*)(dst  ) = make_float4(h[0],h[1],h[2],h[3]);
                *(float4*)(dst+4) = make_float4(h[4],h[5],h[6],h[7]);
            }
        }
    }
}

// ---------------- 4) FFN2: partial = w * (hidden Wd^T) ---------------------
// tile: 64 slots x 128 outdims, K=1024
__global__ __launch_bounds__(256)
void ffn2_kernel(const float* __restrict__ wd) {
    __shared__ float Hs[16][64];
    __shared__ float Ds[16][128];
    __shared__ int toff[NEXP+1], ooff[NEXP+1];

    int tid = threadIdx.x;
    if (tid <= NEXP) { toff[tid] = g_tileoff[tid]; ooff[tid] = g_off[tid]; }
    __syncthreads();
    int nitems = toff[NEXP] * (HDIM/128);    // tiles * 4
    int tx = tid & 15, ty = tid >> 4;
    int lr = tid >> 2, lkq = tid & 3;

    for (int item = blockIdx.x; item < nitems; item += gridDim.x) {
        int tIdx = item >> 2;
        int ht   = item & 3;
        int e = 0;
        while (toff[e+1] <= tIdx) e++;
        int tt    = tIdx - toff[e];
        int base  = ooff[e] + tt*64;
        int nrows = min(64, ooff[e+1] - base);

        const float* hB  = g_hidden + (size_t)base*H2DIM;
        const float* wdB = wd + ((size_t)e*HDIM + (size_t)ht*128)*H2DIM;
        int hr = min(lr, nrows-1);

        unsigned long long acc[4][4] = {};

        for (int k0 = 0; k0 < H2DIM; k0 += 16) {
            float4 ha = *(const float4*)(hB  + (size_t)hr     *H2DIM + k0 + lkq*4);
            float4 d0 = *(const float4*)(wdB + (size_t)lr     *H2DIM + k0 + lkq*4);
            float4 d1 = *(const float4*)(wdB + (size_t)(64+lr)*H2DIM + k0 + lkq*4);
            __syncthreads();
            Hs[lkq*4+0][lr]=ha.x; Hs[lkq*4+1][lr]=ha.y; Hs[lkq*4+2][lr]=ha.z; Hs[lkq*4+3][lr]=ha.w;
            Ds[lkq*4+0][lr]=d0.x; Ds[lkq*4+1][lr]=d0.y; Ds[lkq*4+2][lr]=d0.z; Ds[lkq*4+3][lr]=d0.w;
            Ds[lkq*4+0][64+lr]=d1.x; Ds[lkq*4+1][64+lr]=d1.y; Ds[lkq*4+2][64+lr]=d1.z; Ds[lkq*4+3][64+lr]=d1.w;
            __syncthreads();
#pragma unroll
            for (int kk = 0; kk < 16; kk++) {
                float4 b0 = *(const float4*)&Ds[kk][tx*8];
                float4 b1 = *(const float4*)&Ds[kk][tx*8+4];
                unsigned long long p0 = pk2(b0.x,b0.y), p1 = pk2(b0.z,b0.w);
                unsigned long long p2 = pk2(b1.x,b1.y), p3 = pk2(b1.z,b1.w);
#pragma unroll
                for (int i = 0; i < 4; i++) {
                    float a = Hs[kk][ty*4+i];
                    unsigned long long aa = pk2(a, a);
                    fma2(acc[i][0], aa, p0); fma2(acc[i][1], aa, p1);
                    fma2(acc[i][2], aa, p2); fma2(acc[i][3], aa, p3);
                }
            }
        }
#pragma unroll
        for (int i = 0; i < 4; i++) {
            int row = ty*4 + i;
            if (row < nrows) {
                float tw = g_tw[base + row];
                float o[8];
#pragma unroll
                for (int jp = 0; jp < 4; jp++) {
                    float2 v = upk2(acc[i][jp]);
                    o[2*jp  ] = v.x * tw;
                    o[2*jp+1] = v.y * tw;
                }
                float* dst = g_partial + (size_t)(base+row)*HDIM + ht*128 + tx*8;
                *(float4*)(dst  ) = make_float4(o[0],o[1],o[2],o[3]);
                *(float4*)(dst+4) = make_float4(o[4],o[5],o[6],o[7]);
            }
        }
    }
}

// ---------------- 5) combine: out[t] = sum_k partial[pos[t,k]] -------------
__global__ void combine_kernel(float* __restrict__ out) {
    int idx = blockIdx.x * blockDim.x + threadIdx.x;   // over NTOK*HDIM/4
    if (idx >= NTOK*(HDIM/4)) return;
    int t  = idx / (HDIM/4);
    int h4 = idx - t*(HDIM/4);
    float4 s = make_float4(0.f,0.f,0.f,0.f);
#pragma unroll
    for (int k = 0; k < TOPK; k++) {
        int p = g_pos[t*TOPK + k];
        float4 v = *(const float4*)(g_partial + (size_t)p*HDIM + h4*4);
        s.x += v.x; s.y += v.y; s.z += v.z; s.w += v.w;
    }
    ((float4*)out)[idx] = s;
}

// ---------------- launch ----------------------------------------------------
extern "C" void kernel_launch(void* const* d_in, const int* in_sizes, int n_in,
                              void* d_out, int out_size) {
    const float* x  = (const float*)d_in[0];   // [2,1024,512]
    const float* gw = (const float*)d_in[1];   // [32,512]
    const float* wg = (const float*)d_in[2];   // [32,1024,512]
    const float* wu = (const float*)d_in[3];   // [32,1024,512]
    const float* wd = (const float*)d_in[4];   // [32,512,1024]
    float* out = (float*)d_out;                // [2,1024,512] f32

    gate_kernel   <<<NTOK/8, 256>>>(x, gw);
    route_kernel  <<<1, 256>>>();
    ffn1_kernel   <<<1184, 256>>>(x, wg, wu);
    ffn2_kernel   <<<1184, 256>>>(wd);
    combine_kernel<<<(NTOK*(HDIM/4) + 255)/256, 256>>>(out);
}

// round 3
// speedup vs baseline: 2.3429x; 2.3429x over previous
#include <cuda_runtime.h>
#include <cstdint>

// Problem constants (FractalMoE: E=32, H=512, TOPK=4, B=2, S=1024)
#define NTOK   2048
#define HDIM   512
#define H2DIM  1024
#define NEXP   32
#define TOPK   4
#define NSLOT  (NTOK*TOPK)   // 8192
#define KC     32            // K-chunk per stage

// ---------------- scratch (device globals; no allocation allowed) ----------
__device__ int   g_sel[NSLOT];
__device__ float g_wn[NSLOT];
__device__ int   g_off[NEXP+1];
__device__ int   g_tileoff[NEXP+1];
__device__ int   g_tok[NSLOT];
__device__ float g_tw[NSLOT];
__device__ int   g_pos[NSLOT];
__device__ float g_hidden [(size_t)NSLOT*H2DIM];   // 32 MiB (tf32-rounded values)
__device__ float g_partial[(size_t)NSLOT*HDIM];    // 16 MiB

// ---------------- tf32 helpers ---------------------------------------------
// round-to-nearest fp32 -> tf32 bit pattern (low 13 bits zero)
__device__ __forceinline__ uint32_t rna_tf32(float f) {
    return (__float_as_uint(f) + 0x1000u) & 0xFFFFE000u;
}

// m16n8k8 row.col f32.tf32.tf32.f32
__device__ __forceinline__ void mma8(float d[4], const uint32_t a[4], const uint32_t b[2]) {
    asm volatile(
        "mma.sync.aligned.m16n8k8.row.col.f32.tf32.tf32.f32 "
        "{%0,%1,%2,%3},{%4,%5,%6,%7},{%8,%9},{%0,%1,%2,%3};"
        : "+f"(d[0]), "+f"(d[1]), "+f"(d[2]), "+f"(d[3])
        : "r"(a[0]), "r"(a[1]), "r"(a[2]), "r"(a[3]), "r"(b[0]), "r"(b[1]));
}

// Fragment-major SMEM layout:
//  A panel (128 rows x 32 k): tile (mt 0..7, kt 0..3): 32 lanes x 16B. 16 KB.
//    element (r, kk): mt=r>>4, rin=r&15, kt=kk>>3, kin=kk&7
//    lane=(rin&7)*4+(kin&3), slot=(rin>>3)+2*(kin>>2)
//    off = ((mt*4+kt)*32+lane)*16 + slot*4
//  B panel (Ncols x 32 k): tile (nt, kt): 32 lanes x 8B.
//    element (n, kk): nt=n>>3, nin=n&7; lane=nin*4+(kin&3), slot=kin>>2
//    off = ((nt*4+kt)*32+lane)*8 + slot*4

// ---------------- 1) gating: softmax + top-4 + renormalize -----------------
extern __shared__ char smem_dyn[];

__global__ void gate_kernel(const float* __restrict__ x, const float* __restrict__ gw) {
    float* sgw = (float*)smem_dyn;   // [32][512] = 64KB
    for (int i = threadIdx.x; i < NEXP*HDIM/4; i += blockDim.x)
        ((float4*)sgw)[i] = ((const float4*)gw)[i];
    __syncthreads();
    int warp = threadIdx.x >> 5, lane = threadIdx.x & 31;
    for (int tt = 0; tt < 2; tt++) {
        int t = blockIdx.x*16 + warp*2 + tt;
        const float4* xv = (const float4*)(x + (size_t)t * HDIM);
        const float4* gv = (const float4*)(sgw + lane * HDIM);
        float acc = 0.f;
#pragma unroll 4
        for (int k = 0; k < HDIM/4; k++) {
            float4 a = xv[k], b = gv[k];
            acc += a.x*b.x + a.y*b.y + a.z*b.z + a.w*b.w;
        }
        float m = acc;
        for (int o = 16; o; o >>= 1) m = fmaxf(m, __shfl_xor_sync(0xffffffffu, m, o));
        float p = __expf(acc - m);
        float s = p;
        for (int o = 16; o; o >>= 1) s += __shfl_xor_sync(0xffffffffu, s, o);
        float prob = p / s;

        float cur = prob, wsum = 0.f;
        float wv[TOPK]; int iv[TOPK];
#pragma unroll
        for (int it = 0; it < TOPK; it++) {
            float v = cur; int idx = lane;
            for (int o = 16; o; o >>= 1) {
                float v2 = __shfl_xor_sync(0xffffffffu, v, o);
                int   i2 = __shfl_xor_sync(0xffffffffu, idx, o);
                if (v2 > v || (v2 == v && i2 < idx)) { v = v2; idx = i2; }
            }
            wv[it] = v; iv[it] = idx; wsum += v;
            if (lane == idx) cur = -1.0f;
        }
        if (lane == 0) {
#pragma unroll
            for (int it = 0; it < TOPK; it++) {
                g_sel[t*TOPK + it] = iv[it];
                g_wn [t*TOPK + it] = wv[it] / wsum;
            }
        }
    }
}

// ---------------- 2) routing (tiles of 128 rows) ----------------------------
__global__ void route_kernel() {
    __shared__ int cnt[NEXP], run[NEXP], off_s[NEXP+1];
    int tid = threadIdx.x;
    if (tid < NEXP) { cnt[tid] = 0; run[tid] = 0; }
    __syncthreads();
    for (int i = tid; i < NSLOT; i += blockDim.x)
        atomicAdd(&cnt[g_sel[i]], 1);
    __syncthreads();
    if (tid == 0) {
        int o = 0, to = 0;
        for (int e = 0; e < NEXP; e++) {
            off_s[e] = o; g_off[e] = o; g_tileoff[e] = to;
            o  += cnt[e];
            to += (cnt[e] + 127) >> 7;
        }
        off_s[NEXP] = o; g_off[NEXP] = o; g_tileoff[NEXP] = to;
    }
    __syncthreads();
    for (int i = tid; i < NSLOT; i += blockDim.x) {
        int e = g_sel[i];
        int p = atomicAdd(&run[e], 1) + off_s[e];
        g_tok[p] = i >> 2;
        g_tw [p] = g_wn[i];
        g_pos[i] = p;
    }
}

// ---------------- 3) FFN1: hidden = silu(x Wg^T) * (x Wu^T) -----------------
// item = token-tile (128 rows) x ht (64 hidden cols). Warp tile 32x32 per matrix.
// smem: rtok @0 (512B); A @1024 2x16KB; G @33792 2x8KB; U @50176 2x8KB. tot 66560.
__global__ __launch_bounds__(256)
void ffn1_mma(const float* __restrict__ x,
              const float* __restrict__ wg,
              const float* __restrict__ wu) {
    char* sm = smem_dyn;
    int* rtok = (int*)sm;
    const int tid = threadIdx.x, lane = tid & 31, wid = tid >> 5;
    const int wm = wid >> 1, wn = wid & 1;
    const int sr = tid >> 1, sq = tid & 1;   // A staging: row, k-half
    const int wr = tid >> 2, wq = tid & 3;   // B staging: col(0..63), k-quarter
    const int nitems = g_tileoff[NEXP] * 16;

    for (int item = blockIdx.x; item < nitems; item += gridDim.x) {
        const int tIdx = item >> 4;
        const int ht   = item & 15;
        int e = 0;
        while (g_tileoff[e+1] <= tIdx) e++;
        const int base  = g_off[e] + (tIdx - g_tileoff[e]) * 128;
        const int nrows = min(128, g_off[e+1] - base);

        __syncthreads();
        if (tid < 128) rtok[tid] = g_tok[base + min(tid, nrows-1)];
        __syncthreads();

        const float* wgB = wg + ((size_t)e*H2DIM + (size_t)ht*64) * HDIM;
        const float* wuB = wu + ((size_t)e*H2DIM + (size_t)ht*64) * HDIM;
        const float* xr  = x + (size_t)rtok[sr]*HDIM + sq*16;

        float accG[2][4][4] = {}, accU[2][4][4] = {};
        float4 rA[4], rG[2], rU[2];
#pragma unroll
        for (int i = 0; i < 4; i++) rA[i] = *(const float4*)(xr + i*4);
#pragma unroll
        for (int i = 0; i < 2; i++) {
            rG[i] = *(const float4*)(wgB + (size_t)wr*HDIM + wq*8 + i*4);
            rU[i] = *(const float4*)(wuB + (size_t)wr*HDIM + wq*8 + i*4);
        }

        for (int c = 0; c < HDIM/KC; c++) {
            const int buf = c & 1;
            char* pa = sm + 1024  + buf*16384;
            char* pg = sm + 33792 + buf*8192;
            char* pu = sm + 50176 + buf*8192;
            // ---- STS A (fragment-major scatter) ----
            {
                const int mt = sr >> 4, rin = sr & 15;
                const int lb = (rin & 7) * 4;
                const int sb = (rin >> 3) * 4;
#pragma unroll
                for (int i = 0; i < 4; i++) {
                    const int kt = sq*2 + (i >> 1);
                    const uint32_t so = (uint32_t)(((mt*4+kt)*32 + lb)*16 + sb + (i&1)*8);
                    const float* f = (const float*)&rA[i];
#pragma unroll
                    for (int j = 0; j < 4; j++)
                        *(uint32_t*)(pa + so + j*16) = rna_tf32(f[j]);
                }
            }
            // ---- STS G,U ----
            {
                const int nt = wr >> 3, nin = wr & 7;
#pragma unroll
                for (int i = 0; i < 2; i++) {
                    const uint32_t so = (uint32_t)((((nt*4+wq)*32 + nin*4))*8 + i*4);
                    const float* fg = (const float*)&rG[i];
                    const float* fu = (const float*)&rU[i];
#pragma unroll
                    for (int j = 0; j < 4; j++) {
                        *(uint32_t*)(pg + so + j*8) = rna_tf32(fg[j]);
                        *(uint32_t*)(pu + so + j*8) = rna_tf32(fu[j]);
                    }
                }
            }
            __syncthreads();
            // ---- prefetch next chunk ----
            if (c < HDIM/KC - 1) {
                const int kb = (c+1)*KC;
#pragma unroll
                for (int i = 0; i < 4; i++) rA[i] = *(const float4*)(xr + kb + i*4);
#pragma unroll
                for (int i = 0; i < 2; i++) {
                    rG[i] = *(const float4*)(wgB + (size_t)wr*HDIM + kb + wq*8 + i*4);
                    rU[i] = *(const float4*)(wuB + (size_t)wr*HDIM + kb + wq*8 + i*4);
                }
            }
            // ---- compute 4 k-steps ----
#pragma unroll
            for (int kt = 0; kt < 4; kt++) {
                uint32_t af[2][4], bg[4][2], bu[4][2];
#pragma unroll
                for (int m = 0; m < 2; m++) {
                    uint4 v = *(const uint4*)(pa + (((wm*2+m)*4+kt)*32 + lane)*16);
                    af[m][0]=v.x; af[m][1]=v.y; af[m][2]=v.z; af[m][3]=v.w;
                }
#pragma unroll
                for (int n = 0; n < 4; n++) {
                    uint2 vg = *(const uint2*)(pg + (((wn*4+n)*4+kt)*32 + lane)*8);
                    uint2 vu = *(const uint2*)(pu + (((wn*4+n)*4+kt)*32 + lane)*8);
                    bg[n][0]=vg.x; bg[n][1]=vg.y; bu[n][0]=vu.x; bu[n][1]=vu.y;
                }
#pragma unroll
                for (int m = 0; m < 2; m++)
#pragma unroll
                    for (int n = 0; n < 4; n++) {
                        mma8(accG[m][n], af[m], bg[n]);
                        mma8(accU[m][n], af[m], bu[n]);
                    }
            }
        }
        // ---- epilogue: silu(G)*U -> g_hidden (tf32-rounded) ----
        {
            const int g0 = lane >> 2, q2 = (lane & 3) * 2;
#pragma unroll
            for (int m = 0; m < 2; m++) {
#pragma unroll
                for (int half = 0; half < 2; half++) {
                    const int row = wm*32 + m*16 + g0 + half*8;
                    if (row < nrows) {
                        uint32_t* drow = (uint32_t*)(g_hidden + (size_t)(base+row)*H2DIM
                                                     + ht*64 + wn*32);
#pragma unroll
                        for (int n = 0; n < 4; n++) {
                            float gg0 = accG[m][n][half*2+0], gg1 = accG[m][n][half*2+1];
                            float uu0 = accU[m][n][half*2+0], uu1 = accU[m][n][half*2+1];
                            float h0 = uu0 * gg0 / (1.f + __expf(-gg0));
                            float h1 = uu1 * gg1 / (1.f + __expf(-gg1));
                            uint2 o; o.x = rna_tf32(h0); o.y = rna_tf32(h1);
                            *(uint2*)(drow + n*8 + q2) = o;
                        }
                    }
                }
            }
        }
    }
}

// ---------------- 4) FFN2: partial = tw * (hidden Wd^T) ---------------------
// item = token-tile x ht (128 out cols). Warp tile 32x64 (nt=8). K=1024.
// smem: A @1024 2x16KB; W @33792 2x16KB. tot 66560.
__global__ __launch_bounds__(256)
void ffn2_mma(const float* __restrict__ wd) {
    char* sm = smem_dyn;
    const int tid = threadIdx.x, lane = tid & 31, wid = tid >> 5;
    const int wm = wid >> 1, wn = wid & 1;
    const int sr = tid >> 1, sq = tid & 1;   // A staging: row, k-half
    const int br = tid >> 1, bq = tid & 1;   // B staging: col(0..127), k-half
    const int nitems = g_tileoff[NEXP] * 4;

    for (int item = blockIdx.x; item < nitems; item += gridDim.x) {
        const int tIdx = item >> 2;
        const int ht   = item & 3;
        int e = 0;
        while (g_tileoff[e+1] <= tIdx) e++;
        const int base  = g_off[e] + (tIdx - g_tileoff[e]) * 128;
        const int nrows = min(128, g_off[e+1] - base);

        const float* wdB = wd + ((size_t)e*HDIM + (size_t)ht*128) * H2DIM;
        const float* hr  = g_hidden + (size_t)(base + min(sr, nrows-1))*H2DIM + sq*16;

        float acc[2][8][4] = {};
        float4 rA[4], rB[4];
#pragma unroll
        for (int i = 0; i < 4; i++) {
            rA[i] = *(const float4*)(hr + i*4);
            rB[i] = *(const float4*)(wdB + (size_t)br*H2DIM + bq*16 + i*4);
        }

        for (int c = 0; c < H2DIM/KC; c++) {
            const int buf = c & 1;
            char* pa = sm + 1024  + buf*16384;
            char* pw = sm + 33792 + buf*16384;
            // ---- STS A (already tf32 values; raw bits) ----
            {
                const int mt = sr >> 4, rin = sr & 15;
                const int lb = (rin & 7) * 4;
                const int sb = (rin >> 3) * 4;
#pragma unroll
                for (int i = 0; i < 4; i++) {
                    const int kt = sq*2 + (i >> 1);
                    const uint32_t so = (uint32_t)(((mt*4+kt)*32 + lb)*16 + sb + (i&1)*8);
                    const float* f = (const float*)&rA[i];
#pragma unroll
                    for (int j = 0; j < 4; j++)
                        *(uint32_t*)(pa + so + j*16) = __float_as_uint(f[j]);
                }
            }
            // ---- STS W (rounded) ----
            {
                const int nt = br >> 3, nin = br & 7;
#pragma unroll
                for (int i = 0; i < 4; i++) {
                    const int kt = bq*2 + (i >> 1);
                    const uint32_t so = (uint32_t)(((nt*4+kt)*32 + nin*4)*8 + (i&1)*4);
                    const float* f = (const float*)&rB[i];
#pragma unroll
                    for (int j = 0; j < 4; j++)
                        *(uint32_t*)(pw + so + j*8) = rna_tf32(f[j]);
                }
            }
            __syncthreads();
            if (c < H2DIM/KC - 1) {
                const int kb = (c+1)*KC;
#pragma unroll
                for (int i = 0; i < 4; i++) {
                    rA[i] = *(const float4*)(hr + kb + i*4);
                    rB[i] = *(const float4*)(wdB + (size_t)br*H2DIM + kb + bq*16 + i*4);
                }
            }
            // ---- compute 4 k-steps ----
#pragma unroll
            for (int kt = 0; kt < 4; kt++) {
                uint32_t af[2][4], bw[8][2];
#pragma unroll
                for (int m = 0; m < 2; m++) {
                    uint4 v = *(const uint4*)(pa + (((wm*2+m)*4+kt)*32 + lane)*16);
                    af[m][0]=v.x; af[m][1]=v.y; af[m][2]=v.z; af[m][3]=v.w;
                }
#pragma unroll
                for (int n = 0; n < 8; n++) {
                    uint2 v = *(const uint2*)(pw + (((wn*8+n)*4+kt)*32 + lane)*8);
                    bw[n][0]=v.x; bw[n][1]=v.y;
                }
#pragma unroll
                for (int m = 0; m < 2; m++)
#pragma unroll
                    for (int n = 0; n < 8; n++)
                        mma8(acc[m][n], af[m], bw[n]);
            }
        }
        // ---- epilogue: *tw -> g_partial (exact f32) ----
        {
            const int g0 = lane >> 2, q2 = (lane & 3) * 2;
#pragma unroll
            for (int m = 0; m < 2; m++) {
#pragma unroll
                for (int half = 0; half < 2; half++) {
                    const int row = wm*32 + m*16 + g0 + half*8;
                    if (row < nrows) {
                        const float tw = g_tw[base + row];
                        float* drow = g_partial + (size_t)(base+row)*HDIM
                                      + ht*128 + wn*64;
#pragma unroll
                        for (int n = 0; n < 8; n++) {
                            float2 o;
                            o.x = acc[m][n][half*2+0] * tw;
                            o.y = acc[m][n][half*2+1] * tw;
                            *(float2*)(drow + n*8 + q2) = o;
                        }
                    }
                }
            }
        }
        __syncthreads();
    }
}

// ---------------- 5) combine: out[t] = sum_k partial[pos[t,k]] -------------
__global__ void combine_kernel(float* __restrict__ out) {
    int idx = blockIdx.x * blockDim.x + threadIdx.x;
    if (idx >= NTOK*(HDIM/4)) return;
    int t  = idx / (HDIM/4);
    int h4 = idx - t*(HDIM/4);
    float4 s = make_float4(0.f, 0.f, 0.f, 0.f);
#pragma unroll
    for (int k = 0; k < TOPK; k++) {
        int p = g_pos[t*TOPK + k];
        float4 v = *(const float4*)(g_partial + (size_t)p*HDIM + h4*4);
        s.x += v.x; s.y += v.y; s.z += v.z; s.w += v.w;
    }
    ((float4*)out)[idx] = s;
}

// ---------------- launch ----------------------------------------------------
extern "C" void kernel_launch(void* const* d_in, const int* in_sizes, int n_in,
                              void* d_out, int out_size) {
    const float* x  = (const float*)d_in[0];   // [2,1024,512]
    const float* gw = (const float*)d_in[1];   // [32,512]
    const float* wg = (const float*)d_in[2];   // [32,1024,512]
    const float* wu = (const float*)d_in[3];   // [32,1024,512]
    const float* wd = (const float*)d_in[4];   // [32,512,1024]
    float* out = (float*)d_out;                // [2,1024,512] f32

    cudaFuncSetAttribute(gate_kernel, cudaFuncAttributeMaxDynamicSharedMemorySize, 65536);
    cudaFuncSetAttribute(ffn1_mma,    cudaFuncAttributeMaxDynamicSharedMemorySize, 66560);
    cudaFuncSetAttribute(ffn2_mma,    cudaFuncAttributeMaxDynamicSharedMemorySize, 66560);

    gate_kernel   <<<128, 256, 65536>>>(x, gw);
    route_kernel  <<<1, 256>>>();
    ffn1_mma      <<<296, 256, 66560>>>(x, wg, wu);
    ffn2_mma      <<<296, 256, 66560>>>(wd);
    combine_kernel<<<(NTOK*(HDIM/4) + 255)/256, 256>>>(out);
}

// round 4
// speedup vs baseline: 2.9081x; 1.2412x over previous
#include <cuda_runtime.h>
#include <cstdint>

// Problem constants (FractalMoE: E=32, H=512, TOPK=4, B=2, S=1024)
#define NTOK   2048
#define HDIM   512
#define H2DIM  1024
#define NEXP   32
#define TOPK   4
#define NSLOT  (NTOK*TOPK)   // 8192
#define KC     32            // K-chunk per stage (32 floats = 128B/row)
#define NSTG   3             // cp.async pipeline depth

// ---------------- scratch (device globals; no allocation allowed) ----------
__device__ int   g_sel[NSLOT];
__device__ float g_wn[NSLOT];
__device__ int   g_off[NEXP+1];
__device__ int   g_tileoff[NEXP+1];
__device__ int   g_tok[NSLOT];
__device__ float g_tw[NSLOT];
__device__ int   g_pos[NSLOT];
__device__ float g_hidden [(size_t)NSLOT*H2DIM];   // 32 MiB (tf32-rounded values)
__device__ float g_partial[(size_t)NSLOT*HDIM];    // 16 MiB

// ---------------- helpers ----------------------------------------------------
__device__ __forceinline__ uint32_t rna_tf32(float f) {      // full RN->tf32 bits
    return (__float_as_uint(f) + 0x1000u) & 0xFFFFE000u;
}
__device__ __forceinline__ uint32_t smem_u32(const void* p) {
    uint32_t a;
    asm("{ .reg .u64 t; cvta.to.shared.u64 t, %1; cvt.u32.u64 %0, t; }"
        : "=r"(a) : "l"(p));
    return a;
}
__device__ __forceinline__ void cpa16(uint32_t dst, const void* src) {
    asm volatile("cp.async.cg.shared.global [%0], [%1], 16;" :: "r"(dst), "l"(src));
}
#define CP_COMMIT() asm volatile("cp.async.commit_group;" ::: "memory")
#define CP_WAIT1()  asm volatile("cp.async.wait_group 1;" ::: "memory")

// m16n8k8 row.col f32.tf32.tf32.f32
__device__ __forceinline__ void mma8(float d[4], const uint32_t a[4], const uint32_t b[2]) {
    asm volatile(
        "mma.sync.aligned.m16n8k8.row.col.f32.tf32.tf32.f32 "
        "{%0,%1,%2,%3},{%4,%5,%6,%7},{%8,%9},{%0,%1,%2,%3};"
        : "+f"(d[0]), "+f"(d[1]), "+f"(d[2]), "+f"(d[3])
        : "r"(a[0]), "r"(a[1]), "r"(a[2]), "r"(a[3]), "r"(b[0]), "r"(b[1]));
}

// Panels: row-major, 32 floats (128B) per row. float col c of row r stored at
// c ^ ((r&7)*4)  (16B-block swizzle: block' = (c>>2) ^ (r&7)). Conflict-free for
// both cp.async 16B writes and the 8row x 4col fragment LDS.32 reads.

extern __shared__ char smem_dyn[];

// ---------------- 1) gating: softmax + top-4 + renormalize -----------------
__global__ void gate_kernel(const float* __restrict__ x, const float* __restrict__ gw) {
    float* sgw = (float*)smem_dyn;   // [32][512] = 64KB
    for (int i = threadIdx.x; i < NEXP*HDIM/4; i += blockDim.x)
        ((float4*)sgw)[i] = ((const float4*)gw)[i];
    __syncthreads();
    int warp = threadIdx.x >> 5, lane = threadIdx.x & 31;
    for (int tt = 0; tt < 2; tt++) {
        int t = blockIdx.x*16 + warp*2 + tt;
        const float4* xv = (const float4*)(x + (size_t)t * HDIM);
        const float4* gv = (const float4*)(sgw + lane * HDIM);
        float acc = 0.f;
#pragma unroll 4
        for (int k = 0; k < HDIM/4; k++) {
            float4 a = xv[k], b = gv[k];
            acc += a.x*b.x + a.y*b.y + a.z*b.z + a.w*b.w;
        }
        float m = acc;
        for (int o = 16; o; o >>= 1) m = fmaxf(m, __shfl_xor_sync(0xffffffffu, m, o));
        float p = __expf(acc - m);
        float s = p;
        for (int o = 16; o; o >>= 1) s += __shfl_xor_sync(0xffffffffu, s, o);
        float prob = p / s;

        float cur = prob, wsum = 0.f;
        float wv[TOPK]; int iv[TOPK];
#pragma unroll
        for (int it = 0; it < TOPK; it++) {
            float v = cur; int idx = lane;
            for (int o = 16; o; o >>= 1) {
                float v2 = __shfl_xor_sync(0xffffffffu, v, o);
                int   i2 = __shfl_xor_sync(0xffffffffu, idx, o);
                if (v2 > v || (v2 == v && i2 < idx)) { v = v2; idx = i2; }
            }
            wv[it] = v; iv[it] = idx; wsum += v;
            if (lane == idx) cur = -1.0f;
        }
        if (lane == 0) {
#pragma unroll
            for (int it = 0; it < TOPK; it++) {
                g_sel[t*TOPK + it] = iv[it];
                g_wn [t*TOPK + it] = wv[it] / wsum;
            }
        }
    }
}

// ---------------- 2) routing (tiles of 128 rows) ----------------------------
__global__ void route_kernel() {
    __shared__ int cnt[NEXP], run[NEXP], off_s[NEXP+1];
    int tid = threadIdx.x;
    if (tid < NEXP) { cnt[tid] = 0; run[tid] = 0; }
    __syncthreads();
    for (int i = tid; i < NSLOT; i += blockDim.x)
        atomicAdd(&cnt[g_sel[i]], 1);
    __syncthreads();
    if (tid == 0) {
        int o = 0, to = 0;
        for (int e = 0; e < NEXP; e++) {
            off_s[e] = o; g_off[e] = o; g_tileoff[e] = to;
            o  += cnt[e];
            to += (cnt[e] + 127) >> 7;
        }
        off_s[NEXP] = o; g_off[NEXP] = o; g_tileoff[NEXP] = to;
    }
    __syncthreads();
    for (int i = tid; i < NSLOT; i += blockDim.x) {
        int e = g_sel[i];
        int p = atomicAdd(&run[e], 1) + off_s[e];
        g_tok[p] = i >> 2;
        g_tw [p] = g_wn[i];
        g_pos[i] = p;
    }
}

// ---------------- 3) FFN1: hidden = silu(x Wg^T) * (x Wu^T) -----------------
// tile 128 tok x 64 hid (dual G/U). 8 warps 4m x 2n, warp tile 32x32 per matrix.
// smem: rtok@0; A stages @1024+s*16K; G @50176+s*8K; U @74752+s*8K. tot 99328.
#define F1_A(s)  (1024  + (s)*16384)
#define F1_G(s)  (50176 + (s)*8192)
#define F1_U(s)  (74752 + (s)*8192)

__global__ __launch_bounds__(256)
void ffn1_mma(const float* __restrict__ x,
              const float* __restrict__ wg,
              const float* __restrict__ wu) {
    char* sm = smem_dyn;
    int* rtok = (int*)sm;
    const uint32_t sb = smem_u32(sm);
    const int tid = threadIdx.x, lane = tid & 31, wid = tid >> 5;
    const int wm = wid >> 1, wn = wid & 1;
    const int g0 = lane >> 2, q = lane & 3;
    const int nitems = g_tileoff[NEXP] * 16;

    // copy-thread coords
    const int ar = tid >> 1;                 // A row 0..127
    const int ab = (tid & 1) * 4;            // A block base 0..4
    const int wr_ = tid >> 2;                // G/U row 0..63
    const int wb = (tid & 3) * 2;            // G/U block base

    for (int item = blockIdx.x; item < nitems; item += gridDim.x) {
        const int tIdx = item >> 4;
        const int ht   = item & 15;
        int e = 0;
        while (g_tileoff[e+1] <= tIdx) e++;
        const int base  = g_off[e] + (tIdx - g_tileoff[e]) * 128;
        const int nrows = min(128, g_off[e+1] - base);

        __syncthreads();                      // protect rtok + stage buffers
        if (tid < 128) rtok[tid] = g_tok[base + min(tid, nrows-1)];
        __syncthreads();

        const float* xr  = x + (size_t)rtok[ar]*HDIM;
        const float* wgB = wg + ((size_t)e*H2DIM + (size_t)ht*64) * HDIM + (size_t)wr_*HDIM;
        const float* wuB = wu + ((size_t)e*H2DIM + (size_t)ht*64) * HDIM + (size_t)wr_*HDIM;
        const uint32_t dA = sb + ar*128  + ((ab  ^ (ar &7)) ^ (ab &7) ? 0 : 0); // (placeholder, computed below)
        (void)dA;

        // stage copy lambda
        auto stage = [&](int c) {
            const int s = c % NSTG;
            const int kb = c * KC;
            uint32_t da = sb + F1_A(s) + ar*128;
#pragma unroll
            for (int i = 0; i < 4; i++)
                cpa16(da + ((ab+i) ^ (ar&7))*16, xr + kb + (ab+i)*4);
            uint32_t dg = sb + F1_G(s) + wr_*128;
            uint32_t du = sb + F1_U(s) + wr_*128;
#pragma unroll
            for (int i = 0; i < 2; i++) {
                cpa16(dg + ((wb+i) ^ (wr_&7))*16, wgB + kb + (wb+i)*4);
                cpa16(du + ((wb+i) ^ (wr_&7))*16, wuB + kb + (wb+i)*4);
            }
        };

        float accG[2][4][4] = {}, accU[2][4][4] = {};

        stage(0); CP_COMMIT();
        stage(1); CP_COMMIT();

        for (int c = 0; c < HDIM/KC; c++) {
            CP_WAIT1();
            __syncthreads();
            if (c + 2 < HDIM/KC) stage(c + 2);
            CP_COMMIT();

            const int s = c % NSTG;
            const char* pa = sm + F1_A(s);
            const char* pg = sm + F1_G(s);
            const char* pu = sm + F1_U(s);
            const uint32_t rowA0 = (wm*32 + g0) * 128;
            const uint32_t rowB0 = (wn*32 + g0) * 128;
#pragma unroll
            for (int kt = 0; kt < 4; kt++) {
                const uint32_t co  = (uint32_t)(((kt*8 + q) ^ (g0*4)) * 4);
                const uint32_t co2 = co ^ 16;
                uint32_t a[2][4], bg[4][2], bu[4][2];
#pragma unroll
                for (int m = 0; m < 2; m++) {
                    const char* p = pa + rowA0 + m*2048;      // 16 rows = 2048B
                    a[m][0] = *(const uint32_t*)(p + co)        + 0x1000u;
                    a[m][1] = *(const uint32_t*)(p + 1024 + co) + 0x1000u;
                    a[m][2] = *(const uint32_t*)(p + co2)       + 0x1000u;
                    a[m][3] = *(const uint32_t*)(p + 1024 + co2)+ 0x1000u;
                }
#pragma unroll
                for (int n = 0; n < 4; n++) {
                    const char* pgn = pg + rowB0 + n*1024;    // 8 rows = 1024B
                    const char* pun = pu + rowB0 + n*1024;
                    bg[n][0] = *(const uint32_t*)(pgn + co)  + 0x1000u;
                    bg[n][1] = *(const uint32_t*)(pgn + co2) + 0x1000u;
                    bu[n][0] = *(const uint32_t*)(pun + co)  + 0x1000u;
                    bu[n][1] = *(const uint32_t*)(pun + co2) + 0x1000u;
                }
#pragma unroll
                for (int m = 0; m < 2; m++)
#pragma unroll
                    for (int n = 0; n < 4; n++) {
                        mma8(accG[m][n], a[m], bg[n]);
                        mma8(accU[m][n], a[m], bu[n]);
                    }
            }
        }
        // epilogue: silu(G)*U -> g_hidden (rounded to tf32 so ffn2 skips IADD)
        {
            const int q2 = q * 2;
#pragma unroll
            for (int m = 0; m < 2; m++) {
#pragma unroll
                for (int half = 0; half < 2; half++) {
                    const int row = wm*32 + m*16 + g0 + half*8;
                    if (row < nrows) {
                        uint32_t* drow = (uint32_t*)(g_hidden + (size_t)(base+row)*H2DIM
                                                     + ht*64 + wn*32);
#pragma unroll
                        for (int n = 0; n < 4; n++) {
                            float gg0 = accG[m][n][half*2+0], gg1 = accG[m][n][half*2+1];
                            float uu0 = accU[m][n][half*2+0], uu1 = accU[m][n][half*2+1];
                            float h0 = uu0 * gg0 / (1.f + __expf(-gg0));
                            float h1 = uu1 * gg1 / (1.f + __expf(-gg1));
                            uint2 o; o.x = rna_tf32(h0); o.y = rna_tf32(h1);
                            *(uint2*)(drow + n*8 + q2) = o;
                        }
                    }
                }
            }
        }
    }
}

// ---------------- 4) FFN2: partial = tw * (hidden Wd^T) ---------------------
// tile 128 slots x 128 out. 8 warps 4m x 2n, warp tile 32x64. K=1024.
// smem: A @1024+s*16K; W @50176+s*16K. tot 99328.
#define F2_A(s)  (1024  + (s)*16384)
#define F2_W(s)  (50176 + (s)*16384)

__global__ __launch_bounds__(256)
void ffn2_mma(const float* __restrict__ wd) {
    char* sm = smem_dyn;
    const uint32_t sb = smem_u32(sm);
    const int tid = threadIdx.x, lane = tid & 31, wid = tid >> 5;
    const int wm = wid >> 1, wn = wid & 1;
    const int g0 = lane >> 2, q = lane & 3;
    const int nitems = g_tileoff[NEXP] * 4;

    const int ar = tid >> 1;                 // row 0..127 (A and W identical map)
    const int ab = (tid & 1) * 4;

    for (int item = blockIdx.x; item < nitems; item += gridDim.x) {
        const int tIdx = item >> 2;
        const int ht   = item & 3;
        int e = 0;
        while (g_tileoff[e+1] <= tIdx) e++;
        const int base  = g_off[e] + (tIdx - g_tileoff[e]) * 128;
        const int nrows = min(128, g_off[e+1] - base);

        const float* hr  = g_hidden + (size_t)(base + min(ar, nrows-1))*H2DIM;
        const float* wdB = wd + ((size_t)e*HDIM + (size_t)ht*128) * H2DIM + (size_t)ar*H2DIM;

        __syncthreads();                      // stage-buffer reuse fence

        auto stage = [&](int c) {
            const int s = c % NSTG;
            const int kb = c * KC;
            uint32_t da = sb + F2_A(s) + ar*128;
            uint32_t dw = sb + F2_W(s) + ar*128;
#pragma unroll
            for (int i = 0; i < 4; i++) {
                cpa16(da + ((ab+i) ^ (ar&7))*16, hr  + kb + (ab+i)*4);
                cpa16(dw + ((ab+i) ^ (ar&7))*16, wdB + kb + (ab+i)*4);
            }
        };

        float acc[2][8][4] = {};

        stage(0); CP_COMMIT();
        stage(1); CP_COMMIT();

        for (int c = 0; c < H2DIM/KC; c++) {
            CP_WAIT1();
            __syncthreads();
            if (c + 2 < H2DIM/KC) stage(c + 2);
            CP_COMMIT();

            const int s = c % NSTG;
            const char* pa = sm + F2_A(s);
            const char* pw = sm + F2_W(s);
            const uint32_t rowA0 = (wm*32 + g0) * 128;
            const uint32_t rowB0 = (wn*64 + g0) * 128;
#pragma unroll
            for (int kt = 0; kt < 4; kt++) {
                const uint32_t co  = (uint32_t)(((kt*8 + q) ^ (g0*4)) * 4);
                const uint32_t co2 = co ^ 16;
                uint32_t a[2][4], bw[8][2];
#pragma unroll
                for (int m = 0; m < 2; m++) {
                    const char* p = pa + rowA0 + m*2048;
                    a[m][0] = *(const uint32_t*)(p + co);          // hidden pre-rounded
                    a[m][1] = *(const uint32_t*)(p + 1024 + co);
                    a[m][2] = *(const uint32_t*)(p + co2);
                    a[m][3] = *(const uint32_t*)(p + 1024 + co2);
                }
#pragma unroll
                for (int n = 0; n < 8; n++) {
                    const char* pn = pw + rowB0 + n*1024;
                    bw[n][0] = *(const uint32_t*)(pn + co)  + 0x1000u;
                    bw[n][1] = *(const uint32_t*)(pn + co2) + 0x1000u;
                }
#pragma unroll
                for (int m = 0; m < 2; m++)
#pragma unroll
                    for (int n = 0; n < 8; n++)
                        mma8(acc[m][n], a[m], bw[n]);
            }
        }
        // epilogue: *tw -> g_partial (exact f32)
        {
            const int q2 = q * 2;
#pragma unroll
            for (int m = 0; m < 2; m++) {
#pragma unroll
                for (int half = 0; half < 2; half++) {
                    const int row = wm*32 + m*16 + g0 + half*8;
                    if (row < nrows) {
                        const float tw = g_tw[base + row];
                        float* drow = g_partial + (size_t)(base+row)*HDIM
                                      + ht*128 + wn*64;
#pragma unroll
                        for (int n = 0; n < 8; n++) {
                            float2 o;
                            o.x = acc[m][n][half*2+0] * tw;
                            o.y = acc[m][n][half*2+1] * tw;
                            *(float2*)(drow + n*8 + q2) = o;
                        }
                    }
                }
            }
        }
    }
}

// ---------------- 5) combine: out[t] = sum_k partial[pos[t,k]] -------------
__global__ void combine_kernel(float* __restrict__ out) {
    int idx = blockIdx.x * blockDim.x + threadIdx.x;
    if (idx >= NTOK*(HDIM/4)) return;
    int t  = idx / (HDIM/4);
    int h4 = idx - t*(HDIM/4);
    float4 s = make_float4(0.f, 0.f, 0.f, 0.f);
#pragma unroll
    for (int k = 0; k < TOPK; k++) {
        int p = g_pos[t*TOPK + k];
        float4 v = *(const float4*)(g_partial + (size_t)p*HDIM + h4*4);
        s.x += v.x; s.y += v.y; s.z += v.z; s.w += v.w;
    }
    ((float4*)out)[idx] = s;
}

// ---------------- launch ----------------------------------------------------
extern "C" void kernel_launch(void* const* d_in, const int* in_sizes, int n_in,
                              void* d_out, int out_size) {
    const float* x  = (const float*)d_in[0];   // [2,1024,512]
    const float* gw = (const float*)d_in[1];   // [32,512]
    const float* wg = (const float*)d_in[2];   // [32,1024,512]
    const float* wu = (const float*)d_in[3];   // [32,1024,512]
    const float* wd = (const float*)d_in[4];   // [32,512,1024]
    float* out = (float*)d_out;                // [2,1024,512] f32

    cudaFuncSetAttribute(gate_kernel, cudaFuncAttributeMaxDynamicSharedMemorySize, 65536);
    cudaFuncSetAttribute(ffn1_mma,    cudaFuncAttributeMaxDynamicSharedMemorySize, 99328);
    cudaFuncSetAttribute(ffn2_mma,    cudaFuncAttributeMaxDynamicSharedMemorySize, 99328);

    gate_kernel   <<<128, 256, 65536>>>(x, gw);
    route_kernel  <<<1, 256>>>();
    ffn1_mma      <<<296, 256, 99328>>>(x, wg, wu);
    ffn2_mma      <<<296, 256, 99328>>>(wd);
    combine_kernel<<<(NTOK*(HDIM/4) + 255)/256, 256>>>(out);
}